// round 1
// baseline (speedup 1.0000x reference)
#include <cuda_runtime.h>
#include <math.h>

#define N_NODES 50000
#define N_EDGES 400000
#define N_GRAPHS 512
#define NF 64
#define EF 32
#define AIF 92
#define FCF 128
#define NLAYERS 3
#define TBINS 4096
#define TROWS 4097
#define BN_EPS 1e-5f

// ---------------- scratch (static device memory; no allocations) ----------------
__device__ float d_h[N_NODES * NF];                       // 12.8 MB  node features
__device__ float d_AB[N_NODES * 256];                     // 51.2 MB  [A_i|A_u|B_i|B_u] per node
__device__ __align__(16) float d_agg[N_NODES * NF];       // 12.8 MB  scattered messages
__device__ float d_pre[51200000];                         // 204.8 MB [E,128] pre-activations (i|u)
__device__ float d_table[NLAYERS * TROWS * 128];          // 6.3 MB   RBF@W lookup table
__device__ float d_wbig[NLAYERS * 64 * 256];              // packed node-GEMM weights
__device__ float d_estat[256];                            // edge BN sums: [s1(128)|s2(128)]
__device__ float d_escale[128];
__device__ float d_eshift[128];
__device__ float d_nstat[128];                            // node BN sums: [s1(64)|s2(64)]
__device__ float d_nscale[64];
__device__ float d_nshift[64];

// ---------------- math helpers ----------------
__device__ __forceinline__ float softplus_f(float x) {
    return fmaxf(x, 0.f) + log1pf(expf(-fabsf(x)));
}
__device__ __forceinline__ float sigmoid_f(float x) {
    return 1.f / (1.f + expf(-x));
}

// ---------------- weight packing: Wbig[l][k][c], c: [Ai|Au|Bi|Bu] ----------------
__global__ void k_wbig(const float* __restrict__ Wi, const float* __restrict__ Wu) {
    int idx = blockIdx.x * blockDim.x + threadIdx.x;
    // defensive zero of stat accumulators at launch entry (idempotent)
    if (blockIdx.x == 0) {
        if (threadIdx.x < 256) d_estat[threadIdx.x] = 0.f;
        else if (threadIdx.x < 384) d_nstat[threadIdx.x - 256] = 0.f;
    }
    if (idx >= NLAYERS * 64 * 256) return;
    int l = idx / 16384;
    int r = idx - l * 16384;
    int k = r >> 8;
    int c = r & 255;
    float v;
    if (c < 64)       v = Wi[(l * 160 + k) * 64 + c];          // A_i : h[src] @ Wi[0:64]
    else if (c < 128) v = Wu[(l * 160 + k) * 64 + (c - 64)];   // A_u
    else if (c < 192) v = Wi[(l * 160 + 64 + k) * 64 + (c - 128)]; // B_i : h[dst] @ Wi[64:128]
    else              v = Wu[(l * 160 + 64 + k) * 64 + (c - 192)]; // B_u
    d_wbig[idx] = v;
}

// ---------------- RBF@W lookup table: T[l][t][c] = sum_k exp(-g(d_t-c_k)^2) * W_e[k][c] --------
__global__ void k_table(const float* __restrict__ Wi, const float* __restrict__ Wu) {
    int b = blockIdx.x;
    int l = b / TROWS;
    int t = b - l * TROWS;
    int c = threadIdx.x;            // 0..127
    __shared__ float ek[EF];
    if (c < EF) {
        float d = (float)t * (8.0f / (float)TBINS);
        float ck = (float)c * (8.0f / 31.0f);   // linspace(0,8,32) spacing
        float diff = d - ck;
        ek[c] = expf(-3.875f * diff * diff);    // gamma = 31/8
    }
    __syncthreads();
    const float* W = (c < 64) ? Wi : Wu;
    int cc = c & 63;
    const float* wrow = W + (l * 160 + 128) * 64 + cc;  // e-rows 128..159
    float acc = 0.f;
#pragma unroll
    for (int k = 0; k < EF; k++) acc = fmaf(ek[k], wrow[k * 64], acc);
    d_table[(l * TROWS + t) * 128 + c] = acc;
}

// ---------------- generic small-K GEMM: C[M,N] = A[M,K]@B[K,N] (+bias) --------------
template <int K>
__global__ void __launch_bounds__(256) gemm_k(const float* __restrict__ A,
                                              const float* __restrict__ B,
                                              float* __restrict__ C,
                                              const float* __restrict__ bias,
                                              int M, int N) {
    __shared__ __align__(16) float As[64 * K];
    __shared__ __align__(16) float Bs[K * 64];
    int m0 = blockIdx.x * 64, n0 = blockIdx.y * 64;
    int tid = threadIdx.x;
    for (int idx = tid; idx < 64 * K; idx += 256) {
        int m = idx / K, k = idx - m * K;
        int row = m0 + m;
        As[idx] = (row < M) ? A[(long)row * K + k] : 0.f;
    }
    for (int idx = tid; idx < K * 64; idx += 256) {
        int k = idx >> 6, n = idx & 63;
        Bs[idx] = B[k * N + n0 + n];
    }
    __syncthreads();
    int tx = tid & 15, ty = tid >> 4;
    float acc[4][4] = {};
#pragma unroll 4
    for (int k = 0; k < K; k++) {
        float a0 = As[(ty * 4 + 0) * K + k];
        float a1 = As[(ty * 4 + 1) * K + k];
        float a2 = As[(ty * 4 + 2) * K + k];
        float a3 = As[(ty * 4 + 3) * K + k];
        float4 bv = *(const float4*)&Bs[k * 64 + tx * 4];
        acc[0][0] = fmaf(a0, bv.x, acc[0][0]); acc[0][1] = fmaf(a0, bv.y, acc[0][1]);
        acc[0][2] = fmaf(a0, bv.z, acc[0][2]); acc[0][3] = fmaf(a0, bv.w, acc[0][3]);
        acc[1][0] = fmaf(a1, bv.x, acc[1][0]); acc[1][1] = fmaf(a1, bv.y, acc[1][1]);
        acc[1][2] = fmaf(a1, bv.z, acc[1][2]); acc[1][3] = fmaf(a1, bv.w, acc[1][3]);
        acc[2][0] = fmaf(a2, bv.x, acc[2][0]); acc[2][1] = fmaf(a2, bv.y, acc[2][1]);
        acc[2][2] = fmaf(a2, bv.z, acc[2][2]); acc[2][3] = fmaf(a2, bv.w, acc[2][3]);
        acc[3][0] = fmaf(a3, bv.x, acc[3][0]); acc[3][1] = fmaf(a3, bv.y, acc[3][1]);
        acc[3][2] = fmaf(a3, bv.z, acc[3][2]); acc[3][3] = fmaf(a3, bv.w, acc[3][3]);
    }
#pragma unroll
    for (int i = 0; i < 4; i++) {
        int row = m0 + ty * 4 + i;
        if (row >= M) continue;
#pragma unroll
        for (int j = 0; j < 4; j++) {
            int col = n0 + tx * 4 + j;
            float v = acc[i][j];
            if (bias) v += bias[col];
            C[(long)row * N + col] = v;
        }
    }
}

// ---------------- E1: pre = A[src] + B[dst] + lerp(T, bond); edge BN stats ----------------
__global__ void __launch_bounds__(256) k_E1(const int* __restrict__ src,
                                            const int* __restrict__ dst,
                                            const float* __restrict__ bond,
                                            int layer) {
    int tid = threadIdx.x;
    int c = tid & 127, sub = tid >> 7;

    // fold in zeroing of d_agg for this layer (consumed by E2/N1/N2 later in stream)
    {
        int total4 = (N_NODES * NF) / 4;
        float4 z = make_float4(0.f, 0.f, 0.f, 0.f);
        for (int i = blockIdx.x * 256 + tid; i < total4; i += gridDim.x * 256)
            ((float4*)d_agg)[i] = z;
    }

    const float* T = d_table + layer * TROWS * 128;
    float s1 = 0.f, s2 = 0.f;
    for (int e = blockIdx.x * 2 + sub; e < N_EDGES; e += gridDim.x * 2) {
        int s = __ldg(src + e);
        int d = __ldg(dst + e);
        float bl = __ldg(bond + e);
        float tpos = bl * ((float)TBINS / 8.0f);
        int t0 = min((int)tpos, TBINS - 1);
        float w = tpos - (float)t0;
        float pre = d_AB[s * 256 + c] + d_AB[d * 256 + 128 + c]
                  + (1.f - w) * T[t0 * 128 + c] + w * T[(t0 + 1) * 128 + c];
        d_pre[(long)e * 128 + c] = pre;
        s1 += pre;
        s2 += pre * pre;
    }
    __shared__ float red[512];
    red[tid] = s1;
    red[256 + tid] = s2;
    __syncthreads();
    if (tid < 128) {
        atomicAdd(&d_estat[tid], red[tid] + red[tid + 128]);
        atomicAdd(&d_estat[128 + tid], red[256 + tid] + red[256 + tid + 128]);
    }
}

// ---------------- finalize edge BN (fold affine), reset stats for next layer ------------
__global__ void k_ebn(const float* __restrict__ gi, const float* __restrict__ bti,
                      const float* __restrict__ gu, const float* __restrict__ btu,
                      int layer) {
    int c = threadIdx.x;   // 0..127
    float mean = d_estat[c] / (float)N_EDGES;
    float var = d_estat[128 + c] / (float)N_EDGES - mean * mean;
    float g, bt;
    if (c < 64) { g = gi[layer * 64 + c];       bt = bti[layer * 64 + c]; }
    else        { g = gu[layer * 64 + c - 64];  bt = btu[layer * 64 + c - 64]; }
    float sc = g * rsqrtf(var + BN_EPS);
    d_escale[c] = sc;
    d_eshift[c] = bt - mean * sc;
    d_estat[c] = 0.f;
    d_estat[128 + c] = 0.f;
}

// ---------------- E2: msg = sigmoid(bn_i)*softplus(bn_u); scatter-add by dst ------------
__global__ void __launch_bounds__(256) k_E2(const int* __restrict__ dst) {
    __shared__ float sc[128], sh[128];
    int tid = threadIdx.x;
    if (tid < 128) { sc[tid] = d_escale[tid]; sh[tid] = d_eshift[tid]; }
    __syncthreads();
    int f = tid & 63, sub = tid >> 6;
    for (int e = blockIdx.x * 4 + sub; e < N_EDGES; e += gridDim.x * 4) {
        long base = (long)e * 128;
        float pi = d_pre[base + f];
        float pu = d_pre[base + 64 + f];
        float gate = sigmoid_f(fmaf(pi, sc[f], sh[f]));
        float upd = softplus_f(fmaf(pu, sc[64 + f], sh[64 + f]));
        int dn = __ldg(dst + e);
        atomicAdd(&d_agg[dn * 64 + f], gate * upd);
    }
}

// ---------------- N1: node BN stats over agg ----------------
__global__ void __launch_bounds__(256) k_N1() {
    int tid = threadIdx.x;
    int f = tid & 63, sub = tid >> 6;
    float s1 = 0.f, s2 = 0.f;
    for (int n = blockIdx.x * 4 + sub; n < N_NODES; n += gridDim.x * 4) {
        float v = d_agg[n * 64 + f];
        s1 += v;
        s2 += v * v;
    }
    __shared__ float red[512];
    red[tid] = s1;
    red[256 + tid] = s2;
    __syncthreads();
    if (tid < 64) {
        float a = red[tid] + red[tid + 64] + red[tid + 128] + red[tid + 192];
        float b = red[256 + tid] + red[256 + tid + 64] + red[256 + tid + 128] + red[256 + tid + 192];
        atomicAdd(&d_nstat[tid], a);
        atomicAdd(&d_nstat[64 + tid], b);
    }
}

__global__ void k_nbn(const float* __restrict__ g_bn, const float* __restrict__ b_bn, int layer) {
    int f = threadIdx.x;   // 0..63
    float mean = d_nstat[f] / (float)N_NODES;
    float var = d_nstat[64 + f] / (float)N_NODES - mean * mean;
    float sc = g_bn[layer * 64 + f] * rsqrtf(var + BN_EPS);
    d_nscale[f] = sc;
    d_nshift[f] = b_bn[layer * 64 + f] - mean * sc;
    d_nstat[f] = 0.f;
    d_nstat[64 + f] = 0.f;
}

// ---------------- N2: h = softplus(h + bn(agg)) ----------------
__global__ void __launch_bounds__(256) k_N2() {
    __shared__ float sc[64], sh[64];
    int tid = threadIdx.x;
    if (tid < 64) { sc[tid] = d_nscale[tid]; sh[tid] = d_nshift[tid]; }
    __syncthreads();
    int total = N_NODES * NF;
    for (int i = blockIdx.x * 256 + tid; i < total; i += gridDim.x * 256) {
        int f = i & 63;
        float a = fmaf(d_agg[i], sc[f], sh[f]);
        d_h[i] = softplus_f(d_h[i] + a);
    }
}

// ---------------- final: per-graph mean pool (binary search on sorted ids) + MLP head ----
__device__ __forceinline__ int lbound(const int* a, int n, int v) {
    int lo = 0, hi = n;
    while (lo < hi) {
        int mid = (lo + hi) >> 1;
        if (a[mid] < v) lo = mid + 1; else hi = mid;
    }
    return lo;
}

__global__ void __launch_bounds__(128) k_final(const int* __restrict__ gids,
                                               const float* __restrict__ Wfc,
                                               const float* __restrict__ bfc,
                                               const float* __restrict__ Wout,
                                               const float* __restrict__ bout,
                                               float* __restrict__ out) {
    int g = blockIdx.x;
    int tid = threadIdx.x;
    __shared__ int bounds[2];
    __shared__ float f1s[64];
    __shared__ float red[128];
    if (tid == 0) {
        bounds[0] = lbound(gids, N_NODES, g);
        bounds[1] = lbound(gids, N_NODES, g + 1);
    }
    __syncthreads();
    int lo = bounds[0], hi = bounds[1];
    int f = tid & 63, half = tid >> 6;
    float s = 0.f;
    for (int n = lo + half; n < hi; n += 2) s += d_h[n * 64 + f];
    red[tid] = s;
    __syncthreads();
    if (tid < 64) {
        float tot = red[tid] + red[tid + 64];
        float cnt = (float)max(hi - lo, 1);
        f1s[tid] = softplus_f(tot / cnt);
    }
    __syncthreads();
    float acc = bfc[tid];
#pragma unroll
    for (int k = 0; k < 64; k++) acc = fmaf(f1s[k], Wfc[k * FCF + tid], acc);
    float v = softplus_f(softplus_f(acc)) * Wout[tid];
    red[tid] = v;
    __syncthreads();
    for (int st = 64; st > 0; st >>= 1) {
        if (tid < st) red[tid] += red[tid + st];
        __syncthreads();
    }
    if (tid == 0) out[g] = red[0] + bout[0];
}

// ---------------- launch ----------------
extern "C" void kernel_launch(void* const* d_in, const int* in_sizes, int n_in,
                              void* d_out, int out_size) {
    const float* atom  = (const float*)d_in[0];
    const float* bond  = (const float*)d_in[1];
    const int*   src   = (const int*)d_in[2];
    const int*   dst   = (const int*)d_in[3];
    const int*   gids  = (const int*)d_in[4];
    const float* W_emb = (const float*)d_in[5];
    const float* b_emb = (const float*)d_in[6];
    const float* Wi    = (const float*)d_in[7];
    // d_in[8] = bi  — cancels exactly inside training-mode BatchNorm
    const float* gi    = (const float*)d_in[9];
    const float* bti   = (const float*)d_in[10];
    const float* Wu    = (const float*)d_in[11];
    // d_in[12] = bu — cancels
    const float* gu    = (const float*)d_in[13];
    const float* btu   = (const float*)d_in[14];
    const float* g_bn  = (const float*)d_in[15];
    const float* b_bn  = (const float*)d_in[16];
    const float* W_fc  = (const float*)d_in[17];
    const float* b_fc  = (const float*)d_in[18];
    const float* W_out = (const float*)d_in[19];
    const float* b_out = (const float*)d_in[20];
    float* out = (float*)d_out;

    float *p_h, *p_AB, *p_wbig;
    cudaGetSymbolAddress((void**)&p_h, d_h);
    cudaGetSymbolAddress((void**)&p_AB, d_AB);
    cudaGetSymbolAddress((void**)&p_wbig, d_wbig);

    k_wbig<<<48, 1024>>>(Wi, Wu);
    k_table<<<NLAYERS * TROWS, 128>>>(Wi, Wu);

    // embed: h = atom @ W_emb + b_emb
    gemm_k<AIF><<<dim3(782, 1), 256>>>(atom, W_emb, p_h, b_emb, N_NODES, NF);

    for (int l = 0; l < NLAYERS; l++) {
        // node-level GEMM: AB = h @ Wbig[l]  ([50000,64]@[64,256])
        gemm_k<64><<<dim3(782, 4), 256>>>(p_h, p_wbig + l * 64 * 256, p_AB, nullptr,
                                          N_NODES, 256);
        k_E1<<<1184, 256>>>(src, dst, bond, l);
        k_ebn<<<1, 128>>>(gi, bti, gu, btu, l);
        k_E2<<<1184, 256>>>(dst);
        k_N1<<<1184, 256>>>();
        k_nbn<<<1, 64>>>(g_bn, b_bn, l);
        k_N2<<<1184, 256>>>();
    }

    k_final<<<N_GRAPHS, 128>>>(gids, W_fc, b_fc, W_out, b_out, out);
}

// round 2
// speedup vs baseline: 1.5909x; 1.5909x over previous
#include <cuda_runtime.h>
#include <cuda_fp16.h>
#include <math.h>

#define N_NODES 50000
#define N_EDGES 400000
#define N_GRAPHS 512
#define NF 64
#define EF 32
#define AIF 92
#define FCF 128
#define NLAYERS 3
#define TBINS 4096
#define TROWS 4097
#define BN_EPS 1e-5f

// ---------------- static scratch ----------------
__device__ __align__(16) float   d_h[N_NODES * NF];          // 12.8 MB
__device__ __align__(16) float   d_agg[N_NODES * NF];        // 12.8 MB
__device__ __align__(16) __half2 d_ABp[N_NODES * 128];       // 25.6 MB packed (i,u): [0..63]=A, [64..127]=B
__device__ __align__(16) __half2 d_tab[NLAYERS * TROWS * 64];// 3.1 MB  packed RBF@W table
__device__ __align__(16) float   d_wbig[NLAYERS * 64 * 256]; // packed GEMM weights [Ai|Au|Bi|Bu]
__device__ int   d_counts[N_NODES];
__device__ int   d_rowstart[N_NODES + 1];
__device__ int   d_cursor[N_NODES];
__device__ int   d_csr_eid[N_EDGES];
__device__ int   d_csr_src[N_EDGES];
__device__ float d_csr_bond[N_EDGES];
__device__ float d_estat[256];    // [s1_i|s2_i|s1_u|s2_u] x 64
__device__ float d_escale[128];   // [i|u]
__device__ float d_eshift[128];
__device__ float d_nstat[128];    // [s1|s2] x 64
__device__ float d_nscale[64];
__device__ float d_nshift[64];

// ---------------- fast math ----------------
__device__ __forceinline__ float fsig(float x) {
    return __fdividef(1.f, 1.f + __expf(-x));
}
__device__ __forceinline__ float fsp(float x) {
    return fmaxf(x, 0.f) + __logf(1.f + __expf(-fabsf(x)));
}

// ---------------- prep: pack weights, zero accumulators/counters ----------------
__global__ void k_wbig(const float* __restrict__ Wi, const float* __restrict__ Wu) {
    int tid = threadIdx.x;
    int idx = blockIdx.x * blockDim.x + tid;
    if (blockIdx.x == 0) {
        if (tid < 256) d_estat[tid] = 0.f;
        else if (tid < 384) d_nstat[tid - 256] = 0.f;
    }
    for (int i = idx; i < N_NODES; i += gridDim.x * blockDim.x) d_counts[i] = 0;
    if (idx >= NLAYERS * 64 * 256) return;
    int l = idx / 16384;
    int r = idx - l * 16384;
    int k = r >> 8;
    int c = r & 255;
    float v;
    if (c < 64)       v = Wi[(l * 160 + k) * 64 + c];
    else if (c < 128) v = Wu[(l * 160 + k) * 64 + (c - 64)];
    else if (c < 192) v = Wi[(l * 160 + 64 + k) * 64 + (c - 128)];
    else              v = Wu[(l * 160 + 64 + k) * 64 + (c - 192)];
    d_wbig[idx] = v;
}

// ---------------- RBF@W lookup table (half2 packed: x=i, y=u) ----------------
__global__ void k_table(const float* __restrict__ Wi, const float* __restrict__ Wu) {
    int b = blockIdx.x;
    int l = b / TROWS;
    int t = b - l * TROWS;
    int f = threadIdx.x;   // 0..63
    float d = (float)t * (8.0f / (float)TBINS);
    float ai = 0.f, au = 0.f;
    const float* wi = Wi + (l * 160 + 128) * 64 + f;
    const float* wu = Wu + (l * 160 + 128) * 64 + f;
#pragma unroll
    for (int k = 0; k < EF; k++) {
        float ck = (float)k * (8.0f / 31.0f);
        float diff = d - ck;
        float e = expf(-3.875f * diff * diff);
        ai = fmaf(e, wi[k * 64], ai);
        au = fmaf(e, wu[k * 64], au);
    }
    d_tab[(l * TROWS + t) * 64 + f] = __floats2half2_rn(ai, au);
}

// ---------------- CSR build ----------------
__global__ void k_count(const int* __restrict__ dst) {
    int e = blockIdx.x * blockDim.x + threadIdx.x;
    if (e < N_EDGES) atomicAdd(&d_counts[dst[e]], 1);
}

__global__ void k_scan() {  // single block, 1024 threads
    const int C = 49;       // 1024*49 >= 50000
    int tid = threadIdx.x;
    int base = tid * C;
    int s = 0;
    for (int j = 0; j < C; j++) {
        int i = base + j;
        if (i < N_NODES) s += d_counts[i];
    }
    __shared__ int ss[1024];
    ss[tid] = s;
    __syncthreads();
    for (int off = 1; off < 1024; off <<= 1) {
        int v = (tid >= off) ? ss[tid - off] : 0;
        __syncthreads();
        ss[tid] += v;
        __syncthreads();
    }
    int run = ss[tid] - s;  // exclusive prefix
    for (int j = 0; j < C; j++) {
        int i = base + j;
        if (i < N_NODES) {
            d_rowstart[i] = run;
            d_cursor[i] = run;
            run += d_counts[i];
        }
    }
    if (tid == 0) d_rowstart[N_NODES] = N_EDGES;
}

__global__ void k_fill(const int* __restrict__ dst) {
    int e = blockIdx.x * blockDim.x + threadIdx.x;
    if (e >= N_EDGES) return;
    int pos = atomicAdd(&d_cursor[dst[e]], 1);
    d_csr_eid[pos] = e;
}

// deterministic: sort each node's edge list ascending by edge id
__global__ void k_sort() {
    int n = blockIdx.x * blockDim.x + threadIdx.x;
    if (n >= N_NODES) return;
    int s = d_rowstart[n], e = d_rowstart[n + 1];
    for (int i = s + 1; i < e; i++) {
        int v = d_csr_eid[i];
        int j = i - 1;
        while (j >= s && d_csr_eid[j] > v) {
            d_csr_eid[j + 1] = d_csr_eid[j];
            j--;
        }
        d_csr_eid[j + 1] = v;
    }
}

__global__ void k_csrgather(const int* __restrict__ src, const float* __restrict__ bond) {
    int i = blockIdx.x * blockDim.x + threadIdx.x;
    if (i >= N_EDGES) return;
    int e = d_csr_eid[i];
    d_csr_src[i] = src[e];
    d_csr_bond[i] = bond[e];
}

// ---------------- embed GEMM: d_h = atom[50000,92] @ W_emb[92,64] + b ----------------
__global__ __launch_bounds__(256) void k_gemm_emb(const float* __restrict__ A,
                                                  const float* __restrict__ B,
                                                  const float* __restrict__ bias) {
    __shared__ float As[128 * 32];
    __shared__ float Bs[32 * 64];
    int m0 = blockIdx.x * 128;
    int tid = threadIdx.x;
    int tx = tid & 15, ty = tid >> 4;
    float acc[2][4][4] = {};
    for (int k0 = 0; k0 < AIF; k0 += 32) {
        int kc = min(32, AIF - k0);
        int kc4 = kc >> 2;
#pragma unroll
        for (int it = 0; it < 4; it++) {
            int idx = it * 256 + tid;
            int r = idx >> 3, kk4 = idx & 7;
            if (kk4 < kc4) {
                int row = m0 + r;
                float4 v = (row < N_NODES) ? *(const float4*)&A[row * AIF + k0 + kk4 * 4]
                                           : make_float4(0.f, 0.f, 0.f, 0.f);
                *(float4*)&As[r * 32 + kk4 * 4] = v;
            }
        }
#pragma unroll
        for (int it = 0; it < 2; it++) {
            int idx = it * 256 + tid;
            int kr = idx >> 4, c4 = (idx & 15) * 4;
            if (kr < kc) *(float4*)&Bs[kr * 64 + c4] = *(const float4*)&B[(k0 + kr) * 64 + c4];
        }
        __syncthreads();
#pragma unroll 4
        for (int k = 0; k < kc; k++) {
            float a[2][4], bv[4];
#pragma unroll
            for (int i = 0; i < 4; i++) {
                a[0][i] = As[(ty * 4 + i) * 32 + k];
                a[1][i] = As[(64 + ty * 4 + i) * 32 + k];
            }
            *(float4*)bv = *(float4*)&Bs[k * 64 + tx * 4];
#pragma unroll
            for (int ih = 0; ih < 2; ih++)
#pragma unroll
                for (int i = 0; i < 4; i++)
#pragma unroll
                    for (int j = 0; j < 4; j++)
                        acc[ih][i][j] = fmaf(a[ih][i], bv[j], acc[ih][i][j]);
        }
        __syncthreads();
    }
    float4 bb = *(const float4*)&bias[tx * 4];
#pragma unroll
    for (int ih = 0; ih < 2; ih++)
#pragma unroll
        for (int i = 0; i < 4; i++) {
            int row = m0 + ih * 64 + ty * 4 + i;
            if (row < N_NODES) {
                float4 o;
                o.x = acc[ih][i][0] + bb.x;
                o.y = acc[ih][i][1] + bb.y;
                o.z = acc[ih][i][2] + bb.z;
                o.w = acc[ih][i][3] + bb.w;
                *(float4*)&d_h[row * 64 + tx * 4] = o;
            }
        }
}

// ---------------- layer GEMM: ABp = h[50000,64] @ wbig[l][64,256], packed half2 out ----
__global__ __launch_bounds__(256) void k_gemmAB(int layer) {
    __shared__ float As[128 * 32];
    __shared__ float Bs[32 * 128];
    const float* B = d_wbig + layer * 64 * 256;
    int m0 = blockIdx.x * 128;
    int q = blockIdx.y;          // 0: A-half (cols 0..127), 1: B-half (cols 128..255)
    int n0 = q * 128;
    int tid = threadIdx.x;
    int tx = tid & 15, ty = tid >> 4;
    float acc[2][2][4][4] = {};
    for (int k0 = 0; k0 < 64; k0 += 32) {
#pragma unroll
        for (int it = 0; it < 4; it++) {
            int idx = it * 256 + tid;
            int r = idx >> 3, kk = (idx & 7) * 4;
            int row = m0 + r;
            float4 v = (row < N_NODES) ? *(const float4*)&d_h[row * 64 + k0 + kk]
                                       : make_float4(0.f, 0.f, 0.f, 0.f);
            *(float4*)&As[r * 32 + kk] = v;
        }
#pragma unroll
        for (int it = 0; it < 4; it++) {
            int idx = it * 256 + tid;
            int kr = idx >> 5, c4 = (idx & 31) * 4;
            *(float4*)&Bs[kr * 128 + c4] = *(const float4*)&B[(k0 + kr) * 256 + n0 + c4];
        }
        __syncthreads();
#pragma unroll
        for (int k = 0; k < 32; k++) {
            float a[2][4], b[2][4];
#pragma unroll
            for (int i = 0; i < 4; i++) {
                a[0][i] = As[(ty * 4 + i) * 32 + k];
                a[1][i] = As[(64 + ty * 4 + i) * 32 + k];
            }
            *(float4*)&b[0][0] = *(float4*)&Bs[k * 128 + tx * 4];
            *(float4*)&b[1][0] = *(float4*)&Bs[k * 128 + 64 + tx * 4];
#pragma unroll
            for (int ih = 0; ih < 2; ih++)
#pragma unroll
                for (int jh = 0; jh < 2; jh++)
#pragma unroll
                    for (int i = 0; i < 4; i++)
#pragma unroll
                        for (int j = 0; j < 4; j++)
                            acc[ih][jh][i][j] = fmaf(a[ih][i], b[jh][j], acc[ih][jh][i][j]);
        }
        __syncthreads();
    }
    // jh=0 is the "i" branch, jh=1 is "u": pack into half2(i,u)
#pragma unroll
    for (int ih = 0; ih < 2; ih++)
#pragma unroll
        for (int i = 0; i < 4; i++) {
            int row = m0 + ih * 64 + ty * 4 + i;
            if (row < N_NODES) {
#pragma unroll
                for (int j = 0; j < 4; j++)
                    d_ABp[row * 128 + q * 64 + tx * 4 + j] =
                        __floats2half2_rn(acc[ih][0][i][j], acc[ih][1][i][j]);
            }
        }
}

// ---------------- shared pre computation (identical in stats + apply) ----------------
__device__ __forceinline__ void edge_pre(int sn, float bl, float2 b, const __half2* Tb,
                                         int f, float& pi, float& pu) {
    float2 a = __half22float2(d_ABp[sn * 128 + f]);
    float tpos = bl * ((float)TBINS / 8.0f);
    int t0 = min((int)tpos, TBINS - 1);
    float w = tpos - (float)t0;
    float2 u0 = __half22float2(Tb[t0 * 64 + f]);
    float2 u1 = __half22float2(Tb[t0 * 64 + 64 + f]);
    pi = a.x + b.x + fmaf(w, u1.x - u0.x, u0.x);
    pu = a.y + b.y + fmaf(w, u1.y - u0.y, u0.y);
}

// ---------------- stats pass: edge BN mean/var, node-centric, no stores ----------------
__global__ __launch_bounds__(256) void k_stats(int layer) {
    int tid = threadIdx.x;
    int f = tid & 63, g = tid >> 6;
    const __half2* Tb = d_tab + layer * TROWS * 64;
    float s1i = 0.f, s2i = 0.f, s1u = 0.f, s2u = 0.f;
    for (int n = blockIdx.x * 4 + g; n < N_NODES; n += gridDim.x * 4) {
        int a0 = d_rowstart[n], a1 = d_rowstart[n + 1];
        float2 b = __half22float2(d_ABp[n * 128 + 64 + f]);
        for (int i = a0; i < a1; i++) {
            int sn = d_csr_src[i];
            float bl = d_csr_bond[i];
            float pi, pu;
            edge_pre(sn, bl, b, Tb, f, pi, pu);
            s1i += pi; s2i = fmaf(pi, pi, s2i);
            s1u += pu; s2u = fmaf(pu, pu, s2u);
        }
    }
    __shared__ float red[256];
    red[tid] = s1i; __syncthreads();
    if (tid < 64) atomicAdd(&d_estat[f], red[f] + red[f + 64] + red[f + 128] + red[f + 192]);
    __syncthreads(); red[tid] = s2i; __syncthreads();
    if (tid < 64) atomicAdd(&d_estat[64 + f], red[f] + red[f + 64] + red[f + 128] + red[f + 192]);
    __syncthreads(); red[tid] = s1u; __syncthreads();
    if (tid < 64) atomicAdd(&d_estat[128 + f], red[f] + red[f + 64] + red[f + 128] + red[f + 192]);
    __syncthreads(); red[tid] = s2u; __syncthreads();
    if (tid < 64) atomicAdd(&d_estat[192 + f], red[f] + red[f + 64] + red[f + 128] + red[f + 192]);
}

__global__ void k_ebn(const float* __restrict__ gi, const float* __restrict__ bti,
                      const float* __restrict__ gu, const float* __restrict__ btu,
                      int layer) {
    int c = threadIdx.x;  // 0..127
    float mean, var, g, bt;
    if (c < 64) {
        mean = d_estat[c] / (float)N_EDGES;
        var  = d_estat[64 + c] / (float)N_EDGES - mean * mean;
        g = gi[layer * 64 + c]; bt = bti[layer * 64 + c];
    } else {
        int f = c - 64;
        mean = d_estat[128 + f] / (float)N_EDGES;
        var  = d_estat[192 + f] / (float)N_EDGES - mean * mean;
        g = gu[layer * 64 + f]; bt = btu[layer * 64 + f];
    }
    float sc = g * rsqrtf(var + BN_EPS);
    d_escale[c] = sc;
    d_eshift[c] = bt - mean * sc;
    d_estat[c] = 0.f;
    d_estat[128 + c] = 0.f;
}

// ---------------- apply pass: msg + register aggregation + node BN stats ----------------
__global__ __launch_bounds__(256) void k_apply(int layer) {
    __shared__ float sci[64], shi[64], scu[64], shu[64];
    int tid = threadIdx.x;
    if (tid < 64) {
        sci[tid] = d_escale[tid];      shi[tid] = d_eshift[tid];
        scu[tid] = d_escale[64 + tid]; shu[tid] = d_eshift[64 + tid];
    }
    __syncthreads();
    int f = tid & 63, g = tid >> 6;
    const __half2* Tb = d_tab + layer * TROWS * 64;
    float ci = sci[f], hi = shi[f], cu = scu[f], hu = shu[f];
    float s1 = 0.f, s2 = 0.f;
    for (int n = blockIdx.x * 4 + g; n < N_NODES; n += gridDim.x * 4) {
        int a0 = d_rowstart[n], a1 = d_rowstart[n + 1];
        float2 b = __half22float2(d_ABp[n * 128 + 64 + f]);
        float acc = 0.f;
        for (int i = a0; i < a1; i++) {
            int sn = d_csr_src[i];
            float bl = d_csr_bond[i];
            float pi, pu;
            edge_pre(sn, bl, b, Tb, f, pi, pu);
            float gate = fsig(fmaf(pi, ci, hi));
            float upd = fsp(fmaf(pu, cu, hu));
            acc = fmaf(gate, upd, acc);
        }
        d_agg[n * 64 + f] = acc;
        s1 += acc;
        s2 = fmaf(acc, acc, s2);
    }
    __shared__ float red[256];
    red[tid] = s1; __syncthreads();
    if (tid < 64) atomicAdd(&d_nstat[f], red[f] + red[f + 64] + red[f + 128] + red[f + 192]);
    __syncthreads(); red[tid] = s2; __syncthreads();
    if (tid < 64) atomicAdd(&d_nstat[64 + f], red[f] + red[f + 64] + red[f + 128] + red[f + 192]);
}

__global__ void k_nbn(const float* __restrict__ g_bn, const float* __restrict__ b_bn, int layer) {
    int f = threadIdx.x;  // 0..63
    float mean = d_nstat[f] / (float)N_NODES;
    float var = d_nstat[64 + f] / (float)N_NODES - mean * mean;
    float sc = g_bn[layer * 64 + f] * rsqrtf(var + BN_EPS);
    d_nscale[f] = sc;
    d_nshift[f] = b_bn[layer * 64 + f] - mean * sc;
    d_nstat[f] = 0.f;
    d_nstat[64 + f] = 0.f;
}

__global__ __launch_bounds__(256) void k_N2() {
    __shared__ float sc[64], sh[64];
    int tid = threadIdx.x;
    if (tid < 64) { sc[tid] = d_nscale[tid]; sh[tid] = d_nshift[tid]; }
    __syncthreads();
    int total = N_NODES * NF;
    for (int i = blockIdx.x * 256 + tid; i < total; i += gridDim.x * 256) {
        int f = i & 63;
        float a = fmaf(d_agg[i], sc[f], sh[f]);
        d_h[i] = fsp(d_h[i] + a);
    }
}

// ---------------- final: mean pool per graph + MLP head ----------------
__device__ __forceinline__ int lbound(const int* a, int n, int v) {
    int lo = 0, hi = n;
    while (lo < hi) {
        int mid = (lo + hi) >> 1;
        if (a[mid] < v) lo = mid + 1; else hi = mid;
    }
    return lo;
}

__global__ __launch_bounds__(128) void k_final(const int* __restrict__ gids,
                                               const float* __restrict__ Wfc,
                                               const float* __restrict__ bfc,
                                               const float* __restrict__ Wout,
                                               const float* __restrict__ bout,
                                               float* __restrict__ out) {
    int g = blockIdx.x;
    int tid = threadIdx.x;
    __shared__ int bounds[2];
    __shared__ float f1s[64];
    __shared__ float red[128];
    if (tid == 0) {
        bounds[0] = lbound(gids, N_NODES, g);
        bounds[1] = lbound(gids, N_NODES, g + 1);
    }
    __syncthreads();
    int lo = bounds[0], hi = bounds[1];
    int f = tid & 63, half = tid >> 6;
    float s = 0.f;
    for (int n = lo + half; n < hi; n += 2) s += d_h[n * 64 + f];
    red[tid] = s;
    __syncthreads();
    if (tid < 64) {
        float tot = red[tid] + red[tid + 64];
        float cnt = (float)max(hi - lo, 1);
        f1s[tid] = fsp(tot / cnt);
    }
    __syncthreads();
    float acc = bfc[tid];
#pragma unroll
    for (int k = 0; k < 64; k++) acc = fmaf(f1s[k], Wfc[k * FCF + tid], acc);
    float v = fsp(fsp(acc)) * Wout[tid];
    red[tid] = v;
    __syncthreads();
    for (int st = 64; st > 0; st >>= 1) {
        if (tid < st) red[tid] += red[tid + st];
        __syncthreads();
    }
    if (tid == 0) out[g] = red[0] + bout[0];
}

// ---------------- launch ----------------
extern "C" void kernel_launch(void* const* d_in, const int* in_sizes, int n_in,
                              void* d_out, int out_size) {
    const float* atom  = (const float*)d_in[0];
    const float* bond  = (const float*)d_in[1];
    const int*   src   = (const int*)d_in[2];
    const int*   dst   = (const int*)d_in[3];
    const int*   gids  = (const int*)d_in[4];
    const float* W_emb = (const float*)d_in[5];
    const float* b_emb = (const float*)d_in[6];
    const float* Wi    = (const float*)d_in[7];
    // d_in[8] = bi  — cancels inside training-mode BatchNorm
    const float* gi    = (const float*)d_in[9];
    const float* bti   = (const float*)d_in[10];
    const float* Wu    = (const float*)d_in[11];
    // d_in[12] = bu — cancels
    const float* gu    = (const float*)d_in[13];
    const float* btu   = (const float*)d_in[14];
    const float* g_bn  = (const float*)d_in[15];
    const float* b_bn  = (const float*)d_in[16];
    const float* W_fc  = (const float*)d_in[17];
    const float* b_fc  = (const float*)d_in[18];
    const float* W_out = (const float*)d_in[19];
    const float* b_out = (const float*)d_in[20];
    float* out = (float*)d_out;

    const int EB = (N_EDGES + 255) / 256;   // 1563
    const int NB = (N_NODES + 255) / 256;   // 196

    k_wbig<<<48, 1024>>>(Wi, Wu);
    k_table<<<NLAYERS * TROWS, 64>>>(Wi, Wu);
    k_count<<<EB, 256>>>(dst);
    k_scan<<<1, 1024>>>();
    k_fill<<<EB, 256>>>(dst);
    k_sort<<<NB, 256>>>();
    k_csrgather<<<EB, 256>>>(src, bond);

    k_gemm_emb<<<391, 256>>>(atom, W_emb, b_emb);

    for (int l = 0; l < NLAYERS; l++) {
        k_gemmAB<<<dim3(391, 2), 256>>>(l);
        k_stats<<<1200, 256>>>(l);
        k_ebn<<<1, 128>>>(gi, bti, gu, btu, l);
        k_apply<<<1200, 256>>>(l);
        k_nbn<<<1, 64>>>(g_bn, b_bn, l);
        k_N2<<<12500, 256>>>();
    }

    k_final<<<N_GRAPHS, 128>>>(gids, W_fc, b_fc, W_out, b_out, out);
}

// round 3
// speedup vs baseline: 1.9037x; 1.1966x over previous
#include <cuda_runtime.h>
#include <cuda_fp16.h>
#include <mma.h>
#include <math.h>

using namespace nvcuda;

#define N_NODES 50000
#define NPAD 50048          // 782 * 64, wmma row padding
#define N_EDGES 400000
#define N_GRAPHS 512
#define NF 64
#define EF 32
#define AIF 92
#define FCF 128
#define NLAYERS 3
#define TBINS 16384
#define TROWS 16385
#define BN_EPS 1e-5f

// ---------------- static scratch ----------------
__device__ __align__(16) float   d_h[N_NODES * NF];            // 12.8 MB fp32 node features
__device__ __align__(16) __half  d_hh[NPAD * NF];              // 6.4 MB  fp16 copy for HMMA
__device__ __align__(16) float   d_agg[N_NODES * NF];          // 12.8 MB
__device__ __align__(16) __half2 d_ABp[NPAD * 128];            // 25.6 MB packed (i,u): [0..63]=A, [64..127]=B
__device__ __align__(16) __half2 d_tab[NLAYERS * TROWS * 64];  // 12.6 MB RBF@W table (nearest bin)
__device__ __align__(16) __half  d_wbigh[NLAYERS * 64 * 256];  // fp16 weights, cols interleaved (even=i, odd=u)
__device__ __align__(16) float   d_E[TROWS * EF];              // 2.1 MB  RBF basis matrix
__device__ int   d_counts[N_NODES];
__device__ int   d_rowstart[N_NODES + 1];
__device__ int   d_cursor[N_NODES];
__device__ int   d_bsum[128];
__device__ int   d_boff[128];
__device__ int   d_csr_eid[N_EDGES];
__device__ int   d_csr_src[N_EDGES];
__device__ float d_csr_bond[N_EDGES];
__device__ float d_estat[256];    // [s1_i|s2_i|s1_u|s2_u] x 64
__device__ float d_escale[128];
__device__ float d_eshift[128];
__device__ float d_nstat[128];
__device__ float d_nscale[64];
__device__ float d_nshift[64];

// ---------------- fast math ----------------
__device__ __forceinline__ float fsig(float x) {
    return __fdividef(1.f, 1.f + __expf(-x));
}
__device__ __forceinline__ float fsp(float x) {
    return fmaxf(x, 0.f) + __logf(1.f + __expf(-fabsf(x)));
}

// ---------------- prep: pack fp16 weights (interleaved), zero state ----------------
__global__ void k_wbig(const float* __restrict__ Wi, const float* __restrict__ Wu) {
    int tid = threadIdx.x;
    int idx = blockIdx.x * blockDim.x + tid;
    if (blockIdx.x == 0) {
        if (tid < 256) d_estat[tid] = 0.f;
        else if (tid < 384) d_nstat[tid - 256] = 0.f;
    }
    for (int i = idx; i < N_NODES; i += gridDim.x * blockDim.x) d_counts[i] = 0;
    if (idx >= NLAYERS * 64 * 256) return;
    int l = idx / 16384;
    int r = idx - l * 16384;
    int k = r >> 8;
    int c = r & 255;
    float v;
    if (c < 128) {                       // A-half: gathered via src
        int f = c >> 1;
        int base = (l * 160 + k) * 64 + f;
        v = (c & 1) ? Wu[base] : Wi[base];
    } else {                             // B-half: dst rows 64..127 of W
        int f = (c - 128) >> 1;
        int base = (l * 160 + 64 + k) * 64 + f;
        v = (c & 1) ? Wu[base] : Wi[base];
    }
    d_wbigh[idx] = __float2half(v);
}

// ---------------- RBF basis + table ----------------
__global__ void k_etab() {
    int idx = blockIdx.x * blockDim.x + threadIdx.x;
    if (idx >= TROWS * EF) return;
    int t = idx >> 5, k = idx & 31;
    float d = (float)t * (8.0f / (float)TBINS);
    float ck = (float)k * (8.0f / 31.0f);
    float diff = d - ck;
    d_E[idx] = expf(-3.875f * diff * diff);
}

__global__ void k_table(const float* __restrict__ Wi, const float* __restrict__ Wu) {
    int b = blockIdx.x;
    int l = b / TROWS;
    int t = b - l * TROWS;
    int f = threadIdx.x;   // 0..63
    __shared__ float er[EF];
    if (f < EF) er[f] = d_E[t * EF + f];
    __syncthreads();
    const float* wi = Wi + (l * 160 + 128) * 64 + f;
    const float* wu = Wu + (l * 160 + 128) * 64 + f;
    float ai = 0.f, au = 0.f;
#pragma unroll
    for (int k = 0; k < EF; k++) {
        ai = fmaf(er[k], wi[k * 64], ai);
        au = fmaf(er[k], wu[k * 64], au);
    }
    d_tab[(l * TROWS + t) * 64 + f] = __floats2half2_rn(ai, au);
}

// ---------------- CSR build ----------------
__global__ void k_count(const int* __restrict__ dst) {
    int e = blockIdx.x * blockDim.x + threadIdx.x;
    if (e < N_EDGES) atomicAdd(&d_counts[dst[e]], 1);
}

// 3-phase scan: 98 blocks x 512
__global__ void k_scan1() {
    int b = blockIdx.x, tid = threadIdx.x;
    int i = b * 512 + tid;
    int v = (i < N_NODES) ? d_counts[i] : 0;
    __shared__ int s[512];
    s[tid] = v;
    __syncthreads();
    for (int o = 1; o < 512; o <<= 1) {
        int t = (tid >= o) ? s[tid - o] : 0;
        __syncthreads();
        s[tid] += t;
        __syncthreads();
    }
    if (i < N_NODES) d_rowstart[i] = s[tid] - v;   // block-local exclusive
    if (tid == 511) d_bsum[b] = s[511];
}

__global__ void k_scan2(int nblk) {
    int tid = threadIdx.x;   // 128 threads
    int v = (tid < nblk) ? d_bsum[tid] : 0;
    __shared__ int s[128];
    s[tid] = v;
    __syncthreads();
    for (int o = 1; o < 128; o <<= 1) {
        int t = (tid >= o) ? s[tid - o] : 0;
        __syncthreads();
        s[tid] += t;
        __syncthreads();
    }
    d_boff[tid] = s[tid] - v;
}

__global__ void k_scan3() {
    int i = blockIdx.x * blockDim.x + threadIdx.x;
    if (i >= N_NODES) return;
    int rs = d_rowstart[i] + d_boff[i >> 9];
    d_rowstart[i] = rs;
    d_cursor[i] = rs;
    if (i == 0) d_rowstart[N_NODES] = N_EDGES;
}

__global__ void k_fill(const int* __restrict__ dst) {
    int e = blockIdx.x * blockDim.x + threadIdx.x;
    if (e >= N_EDGES) return;
    int pos = atomicAdd(&d_cursor[dst[e]], 1);
    d_csr_eid[pos] = e;
}

// deterministic per-node order (ascending edge id)
__global__ void k_sort() {
    int n = blockIdx.x * blockDim.x + threadIdx.x;
    if (n >= N_NODES) return;
    int s = d_rowstart[n], e = d_rowstart[n + 1];
    for (int i = s + 1; i < e; i++) {
        int v = d_csr_eid[i];
        int j = i - 1;
        while (j >= s && d_csr_eid[j] > v) {
            d_csr_eid[j + 1] = d_csr_eid[j];
            j--;
        }
        d_csr_eid[j + 1] = v;
    }
}

__global__ void k_csrgather(const int* __restrict__ src, const float* __restrict__ bond) {
    int i = blockIdx.x * blockDim.x + threadIdx.x;
    if (i >= N_EDGES) return;
    int e = d_csr_eid[i];
    d_csr_src[i] = src[e];
    d_csr_bond[i] = bond[e];
}

// ---------------- embed GEMM (fp32 SIMT): h = atom @ W_emb + b ----------------
__global__ __launch_bounds__(256) void k_gemm_emb(const float* __restrict__ A,
                                                  const float* __restrict__ B,
                                                  const float* __restrict__ bias) {
    __shared__ float As[128 * 32];
    __shared__ float Bs[32 * 64];
    int m0 = blockIdx.x * 128;
    int tid = threadIdx.x;
    int tx = tid & 15, ty = tid >> 4;
    float acc[2][4][4] = {};
    for (int k0 = 0; k0 < AIF; k0 += 32) {
        int kc = min(32, AIF - k0);
        int kc4 = kc >> 2;
#pragma unroll
        for (int it = 0; it < 4; it++) {
            int idx = it * 256 + tid;
            int r = idx >> 3, kk4 = idx & 7;
            if (kk4 < kc4) {
                int row = m0 + r;
                float4 v = (row < N_NODES) ? *(const float4*)&A[row * AIF + k0 + kk4 * 4]
                                           : make_float4(0.f, 0.f, 0.f, 0.f);
                *(float4*)&As[r * 32 + kk4 * 4] = v;
            }
        }
#pragma unroll
        for (int it = 0; it < 2; it++) {
            int idx = it * 256 + tid;
            int kr = idx >> 4, c4 = (idx & 15) * 4;
            if (kr < kc) *(float4*)&Bs[kr * 64 + c4] = *(const float4*)&B[(k0 + kr) * 64 + c4];
        }
        __syncthreads();
#pragma unroll 4
        for (int k = 0; k < kc; k++) {
            float a[2][4], bv[4];
#pragma unroll
            for (int i = 0; i < 4; i++) {
                a[0][i] = As[(ty * 4 + i) * 32 + k];
                a[1][i] = As[(64 + ty * 4 + i) * 32 + k];
            }
            *(float4*)bv = *(float4*)&Bs[k * 64 + tx * 4];
#pragma unroll
            for (int ih = 0; ih < 2; ih++)
#pragma unroll
                for (int i = 0; i < 4; i++)
#pragma unroll
                    for (int j = 0; j < 4; j++)
                        acc[ih][i][j] = fmaf(a[ih][i], bv[j], acc[ih][i][j]);
        }
        __syncthreads();
    }
    float4 bb = *(const float4*)&bias[tx * 4];
#pragma unroll
    for (int ih = 0; ih < 2; ih++)
#pragma unroll
        for (int i = 0; i < 4; i++) {
            int row = m0 + ih * 64 + ty * 4 + i;
            if (row < N_NODES) {
                float4 o;
                o.x = acc[ih][i][0] + bb.x;
                o.y = acc[ih][i][1] + bb.y;
                o.z = acc[ih][i][2] + bb.z;
                o.w = acc[ih][i][3] + bb.w;
                *(float4*)&d_h[row * 64 + tx * 4] = o;
                int hb = row * 64 + tx * 4;
                d_hh[hb + 0] = __float2half(o.x);
                d_hh[hb + 1] = __float2half(o.y);
                d_hh[hb + 2] = __float2half(o.z);
                d_hh[hb + 3] = __float2half(o.w);
            }
        }
}

// ---------------- layer GEMM via HMMA: ABp = hh[NPAD,64] @ wbigh[l][64,256] ----------------
__global__ __launch_bounds__(256) void k_gemmAB(int layer) {
    const __half* A = d_hh;
    const __half* B = d_wbigh + layer * 64 * 256;
    int m0 = blockIdx.x * 64;
    int wid = threadIdx.x >> 5;
    int lane = threadIdx.x & 31;
    int mw = wid & 1;        // 2 m-warps * 32 rows
    int nw = wid >> 1;       // 4 n-warps * 64 cols

    wmma::fragment<wmma::accumulator, 16, 16, 16, float> acc[2][4];
#pragma unroll
    for (int mi = 0; mi < 2; mi++)
#pragma unroll
        for (int nj = 0; nj < 4; nj++) wmma::fill_fragment(acc[mi][nj], 0.f);

#pragma unroll
    for (int kk = 0; kk < 4; kk++) {
        wmma::fragment<wmma::matrix_a, 16, 16, 16, __half, wmma::row_major> af[2];
        wmma::fragment<wmma::matrix_b, 16, 16, 16, __half, wmma::row_major> bf[4];
#pragma unroll
        for (int mi = 0; mi < 2; mi++)
            wmma::load_matrix_sync(af[mi], A + (m0 + mw * 32 + mi * 16) * 64 + kk * 16, 64);
#pragma unroll
        for (int nj = 0; nj < 4; nj++)
            wmma::load_matrix_sync(bf[nj], B + (kk * 16) * 256 + nw * 64 + nj * 16, 256);
#pragma unroll
        for (int mi = 0; mi < 2; mi++)
#pragma unroll
            for (int nj = 0; nj < 4; nj++)
                wmma::mma_sync(acc[mi][nj], af[mi], bf[nj], acc[mi][nj]);
    }

    // epilogue: repack fp32 accums into half2(i,u) pairs (cols interleaved even=i odd=u)
    __shared__ float patch[8][256];
    float* p = patch[wid];
#pragma unroll
    for (int mi = 0; mi < 2; mi++)
#pragma unroll
        for (int nj = 0; nj < 4; nj++) {
            wmma::store_matrix_sync(p, acc[mi][nj], 16, wmma::mem_row_major);
            __syncwarp();
            int row0 = m0 + mw * 32 + mi * 16;
            int pairbase = nw * 32 + nj * 8;
#pragma unroll
            for (int j = 0; j < 4; j++) {
                int q = lane * 4 + j;     // 0..127
                int r = q >> 3, pp = q & 7;
                d_ABp[(row0 + r) * 128 + pairbase + pp] =
                    __floats2half2_rn(p[r * 16 + 2 * pp], p[r * 16 + 2 * pp + 1]);
            }
            __syncwarp();
        }
}

// ---------------- per-edge pre (nearest-bin table) ----------------
__device__ __forceinline__ void edge_pre(int sn, float bl, float2 b, const __half2* Tb,
                                         int f, float& pi, float& pu) {
    float2 a = __half22float2(d_ABp[sn * 128 + f]);
    int t = __float2int_rn(bl * ((float)TBINS / 8.0f));   // 0..16384
    float2 u = __half22float2(Tb[t * 64 + f]);
    pi = a.x + b.x + u.x;
    pu = a.y + b.y + u.y;
}

// ---------------- stats pass: edge BN moments ----------------
__global__ __launch_bounds__(256) void k_stats(int layer) {
    int tid = threadIdx.x;
    int f = tid & 63, g = tid >> 6;
    const __half2* Tb = d_tab + layer * TROWS * 64;
    float s1i = 0.f, s2i = 0.f, s1u = 0.f, s2u = 0.f;
    for (int n = blockIdx.x * 4 + g; n < N_NODES; n += gridDim.x * 4) {
        int a0 = d_rowstart[n], a1 = d_rowstart[n + 1];
        float2 b = __half22float2(d_ABp[n * 128 + 64 + f]);
        for (int i = a0; i < a1; i++) {
            int sn = d_csr_src[i];
            float bl = d_csr_bond[i];
            float pi, pu;
            edge_pre(sn, bl, b, Tb, f, pi, pu);
            s1i += pi; s2i = fmaf(pi, pi, s2i);
            s1u += pu; s2u = fmaf(pu, pu, s2u);
        }
    }
    __shared__ float red[256];
    red[tid] = s1i; __syncthreads();
    if (tid < 64) atomicAdd(&d_estat[f], red[f] + red[f + 64] + red[f + 128] + red[f + 192]);
    __syncthreads(); red[tid] = s2i; __syncthreads();
    if (tid < 64) atomicAdd(&d_estat[64 + f], red[f] + red[f + 64] + red[f + 128] + red[f + 192]);
    __syncthreads(); red[tid] = s1u; __syncthreads();
    if (tid < 64) atomicAdd(&d_estat[128 + f], red[f] + red[f + 64] + red[f + 128] + red[f + 192]);
    __syncthreads(); red[tid] = s2u; __syncthreads();
    if (tid < 64) atomicAdd(&d_estat[192 + f], red[f] + red[f + 64] + red[f + 128] + red[f + 192]);
}

__global__ void k_ebn(const float* __restrict__ gi, const float* __restrict__ bti,
                      const float* __restrict__ gu, const float* __restrict__ btu,
                      int layer) {
    int c = threadIdx.x;  // 0..127
    float mean, var, g, bt;
    if (c < 64) {
        mean = d_estat[c] / (float)N_EDGES;
        var  = d_estat[64 + c] / (float)N_EDGES - mean * mean;
        g = gi[layer * 64 + c]; bt = bti[layer * 64 + c];
    } else {
        int f = c - 64;
        mean = d_estat[128 + f] / (float)N_EDGES;
        var  = d_estat[192 + f] / (float)N_EDGES - mean * mean;
        g = gu[layer * 64 + f]; bt = btu[layer * 64 + f];
    }
    float sc = g * rsqrtf(var + BN_EPS);
    d_escale[c] = sc;
    d_eshift[c] = bt - mean * sc;
    d_estat[c] = 0.f;
    d_estat[128 + c] = 0.f;
}

// ---------------- apply pass: messages + register aggregation + node BN stats ----------------
__global__ __launch_bounds__(256) void k_apply(int layer) {
    __shared__ float sci[64], shi[64], scu[64], shu[64];
    int tid = threadIdx.x;
    if (tid < 64) {
        sci[tid] = d_escale[tid];      shi[tid] = d_eshift[tid];
        scu[tid] = d_escale[64 + tid]; shu[tid] = d_eshift[64 + tid];
    }
    __syncthreads();
    int f = tid & 63, g = tid >> 6;
    const __half2* Tb = d_tab + layer * TROWS * 64;
    float ci = sci[f], hi = shi[f], cu = scu[f], hu = shu[f];
    float s1 = 0.f, s2 = 0.f;
    for (int n = blockIdx.x * 4 + g; n < N_NODES; n += gridDim.x * 4) {
        int a0 = d_rowstart[n], a1 = d_rowstart[n + 1];
        float2 b = __half22float2(d_ABp[n * 128 + 64 + f]);
        float acc = 0.f;
        for (int i = a0; i < a1; i++) {
            int sn = d_csr_src[i];
            float bl = d_csr_bond[i];
            float pi, pu;
            edge_pre(sn, bl, b, Tb, f, pi, pu);
            float gate = fsig(fmaf(pi, ci, hi));
            float upd = fsp(fmaf(pu, cu, hu));
            acc = fmaf(gate, upd, acc);
        }
        d_agg[n * 64 + f] = acc;
        s1 += acc;
        s2 = fmaf(acc, acc, s2);
    }
    __shared__ float red[256];
    red[tid] = s1; __syncthreads();
    if (tid < 64) atomicAdd(&d_nstat[f], red[f] + red[f + 64] + red[f + 128] + red[f + 192]);
    __syncthreads(); red[tid] = s2; __syncthreads();
    if (tid < 64) atomicAdd(&d_nstat[64 + f], red[f] + red[f + 64] + red[f + 128] + red[f + 192]);
}

__global__ void k_nbn(const float* __restrict__ g_bn, const float* __restrict__ b_bn, int layer) {
    int f = threadIdx.x;  // 0..63
    float mean = d_nstat[f] / (float)N_NODES;
    float var = d_nstat[64 + f] / (float)N_NODES - mean * mean;
    float sc = g_bn[layer * 64 + f] * rsqrtf(var + BN_EPS);
    d_nscale[f] = sc;
    d_nshift[f] = b_bn[layer * 64 + f] - mean * sc;
    d_nstat[f] = 0.f;
    d_nstat[64 + f] = 0.f;
}

__global__ __launch_bounds__(256) void k_N2() {
    __shared__ float sc[64], sh[64];
    int tid = threadIdx.x;
    if (tid < 64) { sc[tid] = d_nscale[tid]; sh[tid] = d_nshift[tid]; }
    __syncthreads();
    int total = N_NODES * NF;
    for (int i = blockIdx.x * 256 + tid; i < total; i += gridDim.x * 256) {
        int f = i & 63;
        float a = fmaf(d_agg[i], sc[f], sh[f]);
        float v = fsp(d_h[i] + a);
        d_h[i] = v;
        d_hh[i] = __float2half(v);
    }
}

// ---------------- final: mean pool per graph + MLP head ----------------
__device__ __forceinline__ int lbound(const int* a, int n, int v) {
    int lo = 0, hi = n;
    while (lo < hi) {
        int mid = (lo + hi) >> 1;
        if (a[mid] < v) lo = mid + 1; else hi = mid;
    }
    return lo;
}

__global__ __launch_bounds__(128) void k_final(const int* __restrict__ gids,
                                               const float* __restrict__ Wfc,
                                               const float* __restrict__ bfc,
                                               const float* __restrict__ Wout,
                                               const float* __restrict__ bout,
                                               float* __restrict__ out) {
    int g = blockIdx.x;
    int tid = threadIdx.x;
    __shared__ int bounds[2];
    __shared__ float f1s[64];
    __shared__ float red[128];
    if (tid == 0) {
        bounds[0] = lbound(gids, N_NODES, g);
        bounds[1] = lbound(gids, N_NODES, g + 1);
    }
    __syncthreads();
    int lo = bounds[0], hi = bounds[1];
    int f = tid & 63, half = tid >> 6;
    float s = 0.f;
    for (int n = lo + half; n < hi; n += 2) s += d_h[n * 64 + f];
    red[tid] = s;
    __syncthreads();
    if (tid < 64) {
        float tot = red[tid] + red[tid + 64];
        float cnt = (float)max(hi - lo, 1);
        f1s[tid] = fsp(tot / cnt);
    }
    __syncthreads();
    float acc = bfc[tid];
#pragma unroll
    for (int k = 0; k < 64; k++) acc = fmaf(f1s[k], Wfc[k * FCF + tid], acc);
    float v = fsp(fsp(acc)) * Wout[tid];
    red[tid] = v;
    __syncthreads();
    for (int st = 64; st > 0; st >>= 1) {
        if (tid < st) red[tid] += red[tid + st];
        __syncthreads();
    }
    if (tid == 0) out[g] = red[0] + bout[0];
}

// ---------------- launch ----------------
extern "C" void kernel_launch(void* const* d_in, const int* in_sizes, int n_in,
                              void* d_out, int out_size) {
    const float* atom  = (const float*)d_in[0];
    const float* bond  = (const float*)d_in[1];
    const int*   src   = (const int*)d_in[2];
    const int*   dst   = (const int*)d_in[3];
    const int*   gids  = (const int*)d_in[4];
    const float* W_emb = (const float*)d_in[5];
    const float* b_emb = (const float*)d_in[6];
    const float* Wi    = (const float*)d_in[7];
    // d_in[8] = bi  — cancels inside training-mode BatchNorm
    const float* gi    = (const float*)d_in[9];
    const float* bti   = (const float*)d_in[10];
    const float* Wu    = (const float*)d_in[11];
    // d_in[12] = bu — cancels
    const float* gu    = (const float*)d_in[13];
    const float* btu   = (const float*)d_in[14];
    const float* g_bn  = (const float*)d_in[15];
    const float* b_bn  = (const float*)d_in[16];
    const float* W_fc  = (const float*)d_in[17];
    const float* b_fc  = (const float*)d_in[18];
    const float* W_out = (const float*)d_in[19];
    const float* b_out = (const float*)d_in[20];
    float* out = (float*)d_out;

    const int EB = (N_EDGES + 255) / 256;   // 1563
    const int NB = (N_NODES + 255) / 256;   // 196
    const int SB = (N_NODES + 511) / 512;   // 98

    k_wbig<<<48, 1024>>>(Wi, Wu);
    k_etab<<<(TROWS * EF + 255) / 256, 256>>>();
    k_table<<<NLAYERS * TROWS, 64>>>(Wi, Wu);
    k_count<<<EB, 256>>>(dst);
    k_scan1<<<SB, 512>>>();
    k_scan2<<<1, 128>>>(SB);
    k_scan3<<<SB, 512>>>();
    k_fill<<<EB, 256>>>(dst);
    k_sort<<<NB, 256>>>();
    k_csrgather<<<EB, 256>>>(src, bond);

    k_gemm_emb<<<391, 256>>>(atom, W_emb, b_emb);

    for (int l = 0; l < NLAYERS; l++) {
        k_gemmAB<<<NPAD / 64, 256>>>(l);
        k_stats<<<1200, 256>>>(l);
        k_ebn<<<1, 128>>>(gi, bti, gu, btu, l);
        k_apply<<<1200, 256>>>(l);
        k_nbn<<<1, 64>>>(g_bn, b_bn, l);
        k_N2<<<2048, 256>>>();
    }

    k_final<<<N_GRAPHS, 128>>>(gids, W_fc, b_fc, W_out, b_out, out);
}